// round 5
// baseline (speedup 1.0000x reference)
#include <cuda_runtime.h>

// ---------------- problem constants (fixed by the dataset) ----------------
#define NN   50000          // nodes
#define EE   600000         // edges
#define HD   256            // feature dim (DIN == H == 256)
#define NG   64             // graphs
#define SCAN_B 1024
#define NBLK ((NN + SCAN_B - 1) / SCAN_B)   // 49

// ---------------- device scratch (no allocations allowed) -----------------
__device__ float g_bufA[NN * HD];     // h (layer output)
__device__ float g_bufB[NN * HD];     // hw (GEMM output)
__device__ float g_deg[NN];
__device__ float g_dinv[NN];
__device__ int   g_rowptr[NN + 1];
__device__ int   g_cnt[NN];
__device__ int   g_fill[NN];
__device__ int   g_col[EE];
__device__ float g_val[EE];
__device__ int   g_gstart[NG + 1];
__device__ float g_pool[NG * HD];
__device__ int   g_bsum[64];

// ---------------- packed f32x2 FMA helpers --------------------------------
__device__ __forceinline__ unsigned long long pack2(float lo, float hi) {
    unsigned long long r;
    asm("mov.b64 %0, {%1, %2};" : "=l"(r) : "f"(lo), "f"(hi));
    return r;
}
__device__ __forceinline__ void fma2(unsigned long long& d,
                                     unsigned long long a,
                                     unsigned long long b) {
    asm("fma.rn.f32x2 %0, %1, %2, %0;" : "+l"(d) : "l"(a), "l"(b));
}

// ---------------- setup kernels -------------------------------------------
__global__ void init_nodes_kernel() {
    int i = blockIdx.x * blockDim.x + threadIdx.x;
    if (i < NN) { g_deg[i] = 1.0f; g_cnt[i] = 0; g_fill[i] = 0; }
}

__global__ void count_kernel(const int* __restrict__ ei) {
    int e = blockIdx.x * blockDim.x + threadIdx.x;
    if (e < EE) {
        int d = ei[EE + e];
        atomicAdd(&g_deg[d], 1.0f);
        atomicAdd(&g_cnt[d], 1);
    }
}

__global__ void dinv_kernel() {
    int i = blockIdx.x * blockDim.x + threadIdx.x;
    if (i < NN) g_dinv[i] = rsqrtf(g_deg[i]);   // deg >= 1 always (self loop)
}

// 3-pass exclusive scan of g_cnt -> g_rowptr
__global__ void scan1_kernel() {
    __shared__ int sh[SCAN_B];
    int b = blockIdx.x, t = threadIdx.x;
    int i = b * SCAN_B + t;
    sh[t] = (i < NN) ? g_cnt[i] : 0;
    __syncthreads();
    #pragma unroll
    for (int off = 1; off < SCAN_B; off <<= 1) {
        int x = (t >= off) ? sh[t - off] : 0;
        __syncthreads();
        sh[t] += x;
        __syncthreads();
    }
    if (i < NN) g_rowptr[i + 1] = sh[t];          // inclusive within block
    if (t == SCAN_B - 1) g_bsum[b] = sh[t];
}

__global__ void scan2_kernel() {
    __shared__ int sh[64];
    int t = threadIdx.x;
    sh[t] = (t < NBLK) ? g_bsum[t] : 0;
    __syncthreads();
    #pragma unroll
    for (int off = 1; off < 64; off <<= 1) {
        int x = (t >= off) ? sh[t - off] : 0;
        __syncthreads();
        sh[t] += x;
        __syncthreads();
    }
    g_bsum[t] = (t == 0) ? 0 : sh[t - 1];         // exclusive block offsets
}

__global__ void scan3_kernel() {
    int b = blockIdx.x, t = threadIdx.x;
    int i = b * SCAN_B + t;
    if (i < NN) g_rowptr[i + 1] += g_bsum[b];
    if (b == 0 && t == 0) g_rowptr[0] = 0;
}

__global__ void fill_kernel(const int* __restrict__ ei) {
    int e = blockIdx.x * blockDim.x + threadIdx.x;
    if (e < EE) {
        int s = ei[e];
        int d = ei[EE + e];
        int p = g_rowptr[d] + atomicAdd(&g_fill[d], 1);
        g_col[p] = s;
        g_val[p] = g_dinv[s];
    }
}

// graph boundaries: batch is sorted, binary search per graph id
__global__ void gstart_kernel(const int* __restrict__ batch) {
    int g = threadIdx.x;                 // launched with 65 threads
    if (g > NG) return;
    int lo = 0, hi = NN;
    while (lo < hi) {
        int mid = (lo + hi) >> 1;
        if (batch[mid] < g) lo = mid + 1; else hi = mid;
    }
    g_gstart[g] = lo;
}

// ---------------- GEMM: C[M,256] = A[M,256] @ W[256,256] (f32x2 FFMA) -----
#define BM 128
#define BN 128
#define BK 16

__global__ void __launch_bounds__(256)
gemm_kernel(const float* __restrict__ A, const float* __restrict__ W,
            float* __restrict__ C, int M) {
    __shared__ float As[BK][BM + 4];
    __shared__ float Bs[BK][BN];

    int tid = threadIdx.x;
    int bm = blockIdx.x * BM;
    int bn = blockIdx.y * BN;
    int tx = tid & 15, ty = tid >> 4;
    int m0 = ty * 8, n0 = tx * 8;

    unsigned long long acc[8][4];
    unsigned long long zz = pack2(0.0f, 0.0f);
    #pragma unroll
    for (int i = 0; i < 8; i++)
        #pragma unroll
        for (int j = 0; j < 4; j++) acc[i][j] = zz;

    for (int kt = 0; kt < 256; kt += BK) {
        // A tile: 128x16 = 512 float4, 2 per thread; store transposed
        #pragma unroll
        for (int l = 0; l < 2; l++) {
            int f = tid + l * 256;
            int r = f >> 2, kq = (f & 3) * 4;
            int gr = bm + r;
            float4 v = make_float4(0.f, 0.f, 0.f, 0.f);
            if (gr < M) v = *(const float4*)&A[gr * 256 + kt + kq];
            As[kq + 0][r] = v.x; As[kq + 1][r] = v.y;
            As[kq + 2][r] = v.z; As[kq + 3][r] = v.w;
        }
        // B tile: 16x128 = 512 float4, 2 per thread
        #pragma unroll
        for (int l = 0; l < 2; l++) {
            int f = tid + l * 256;
            int k = f >> 5, c = (f & 31) * 4;
            *(float4*)&Bs[k][c] = *(const float4*)&W[(kt + k) * 256 + bn + c];
        }
        __syncthreads();
        #pragma unroll
        for (int k = 0; k < BK; k++) {
            unsigned long long b2[4];
            #pragma unroll
            for (int j = 0; j < 4; j++)
                b2[j] = *(const unsigned long long*)&Bs[k][n0 + 2 * j];
            #pragma unroll
            for (int i = 0; i < 8; i++) {
                float a = As[k][m0 + i];
                unsigned long long a2 = pack2(a, a);
                #pragma unroll
                for (int j = 0; j < 4; j++) fma2(acc[i][j], a2, b2[j]);
            }
        }
        __syncthreads();
    }

    #pragma unroll
    for (int i = 0; i < 8; i++) {
        int gr = bm + m0 + i;
        if (gr < M) {
            #pragma unroll
            for (int j = 0; j < 4; j++)
                *(unsigned long long*)&C[gr * 256 + bn + n0 + 2 * j] = acc[i][j];
        }
    }
}

// ---------------- aggregation: out = relu(dinv_d*(Σ val*hw[col] + dinv_d*hw[d]) + b)
__global__ void __launch_bounds__(HD)
agg_kernel(const float* __restrict__ hw, const float* __restrict__ bias,
           float* __restrict__ out) {
    int node = blockIdx.x;
    int t = threadIdx.x;                 // 256 threads, one feature each
    int beg = g_rowptr[node], end = g_rowptr[node + 1];
    float di = g_dinv[node];
    float acc = di * hw[node * HD + t];  // self-loop term
    for (int p = beg; p < end; p++) {
        int s = g_col[p];                // uniform per block -> broadcast load
        float w = g_val[p];
        acc += w * hw[s * HD + t];       // coalesced 1KB row gather
    }
    out[node * HD + t] = fmaxf(fmaf(acc, di, bias[t]), 0.0f);
}

// ---------------- mean pool per graph (batch is sorted: contiguous ranges)
__global__ void pool_kernel(const float* __restrict__ h) {
    int g = blockIdx.x, t = threadIdx.x; // 256 threads
    int s = g_gstart[g], e = g_gstart[g + 1];
    float acc = 0.0f;
    for (int n = s; n < e; n++) acc += h[n * HD + t];
    float c = (float)(e - s);
    g_pool[g * HD + t] = acc / fmaxf(c, 1.0f);
}

// ---------------- classifier head: [64,256]@[256,128] relu @[128,16] ------
__global__ void __launch_bounds__(128)
classifier_kernel(const float* __restrict__ cW1, const float* __restrict__ cb1,
                  const float* __restrict__ cW2, const float* __restrict__ cb2,
                  float* __restrict__ out) {
    __shared__ float sp[HD];
    __shared__ float sz[128];
    int g = blockIdx.x, t = threadIdx.x; // 128 threads
    sp[t]       = g_pool[g * HD + t];
    sp[t + 128] = g_pool[g * HD + t + 128];
    __syncthreads();
    float acc = cb1[t];
    #pragma unroll 4
    for (int k = 0; k < HD; k++) acc = fmaf(sp[k], cW1[k * 128 + t], acc);
    sz[t] = fmaxf(acc, 0.0f);
    __syncthreads();
    if (t < 16) {
        float a = cb2[t];
        #pragma unroll 4
        for (int j = 0; j < 128; j++) a = fmaf(sz[j], cW2[j * 16 + t], a);
        out[g * 16 + t] = a;
    }
}

// ---------------- launch --------------------------------------------------
extern "C" void kernel_launch(void* const* d_in, const int* in_sizes, int n_in,
                              void* d_out, int out_size) {
    // Bind inputs by element count (robust to metadata ordering).
    // Same-size groups (W0/W1/W2, b0/b1/b2) keep encounter order.
    const void* p_x = 0;  const void* p_ei = 0;  const void* p_batch = 0;
    const void* p_W[3] = {0,0,0}; int nW = 0;
    const void* p_b[3] = {0,0,0}; int nb = 0;
    const void* p_cW1 = 0; const void* p_cb1 = 0;
    const void* p_cW2 = 0; const void* p_cb2 = 0;
    for (int i = 0; i < n_in; i++) {
        int sz = in_sizes[i];
        const void* p = d_in[i];
        if      (sz == NN * HD)   p_x = p;            // 12,800,000
        else if (sz == 2 * EE)    p_ei = p;           // 1,200,000
        else if (sz == NN)        p_batch = p;        // 50,000
        else if (sz == HD * HD)   { if (nW < 3) p_W[nW++] = p; }   // 65,536
        else if (sz == HD)        { if (nb < 3) p_b[nb++] = p; }   // 256
        else if (sz == HD * 128)  p_cW1 = p;          // 32,768
        else if (sz == 128)       p_cb1 = p;
        else if (sz == 128 * 16)  p_cW2 = p;          // 2,048
        else if (sz == 16)        p_cb2 = p;
    }

    const float* x     = (const float*)p_x;
    const int*   ei    = (const int*)p_ei;      // JAX default x64-off: int32
    const int*   batch = (const int*)p_batch;
    const float* W0 = (const float*)p_W[0]; const float* b0 = (const float*)p_b[0];
    const float* W1 = (const float*)p_W[1]; const float* b1 = (const float*)p_b[1];
    const float* W2 = (const float*)p_W[2]; const float* b2 = (const float*)p_b[2];
    const float* cW1 = (const float*)p_cW1; const float* cb1 = (const float*)p_cb1;
    const float* cW2 = (const float*)p_cW2; const float* cb2 = (const float*)p_cb2;
    float* out = (float*)d_out;

    float* bufA;  cudaGetSymbolAddress((void**)&bufA, g_bufA);
    float* bufB;  cudaGetSymbolAddress((void**)&bufB, g_bufB);

    // --- graph structure (recomputed every replay; cheap) ---
    init_nodes_kernel<<<(NN + 255) / 256, 256>>>();
    count_kernel<<<(EE + 255) / 256, 256>>>(ei);
    dinv_kernel<<<(NN + 255) / 256, 256>>>();
    scan1_kernel<<<NBLK, SCAN_B>>>();
    scan2_kernel<<<1, 64>>>();
    scan3_kernel<<<NBLK, SCAN_B>>>();
    fill_kernel<<<(EE + 255) / 256, 256>>>(ei);
    gstart_kernel<<<1, NG + 1>>>(batch);

    dim3 ggrid((NN + BM - 1) / BM, 256 / BN);

    // --- layer 1 ---
    gemm_kernel<<<ggrid, 256>>>(x, W0, bufB, NN);
    agg_kernel<<<NN, HD>>>(bufB, b0, bufA);
    // --- layer 2 ---
    gemm_kernel<<<ggrid, 256>>>(bufA, W1, bufB, NN);
    agg_kernel<<<NN, HD>>>(bufB, b1, bufA);
    // --- layer 3 ---
    gemm_kernel<<<ggrid, 256>>>(bufA, W2, bufB, NN);
    agg_kernel<<<NN, HD>>>(bufB, b2, bufA);

    // --- pool + head ---
    pool_kernel<<<NG, HD>>>(bufA);
    classifier_kernel<<<NG, 128>>>(cW1, cb1, cW2, cb2, out);
}

// round 8
// speedup vs baseline: 1.3579x; 1.3579x over previous
#include <cuda_runtime.h>
#include <cuda_bf16.h>
#include <cstdint>

// ---------------- problem constants ----------------
#define NN   50000
#define EE   600000
#define HD   256
#define NG   64
#define SCAN_B 1024
#define NBLK ((NN + SCAN_B - 1) / SCAN_B)   // 49
#define MTILES ((NN + 127) / 128)           // 391

// ---------------- device scratch -------------------
__device__ float g_bufA[NN * HD];          // layer output (f32)
__device__ float g_bufB[NN * HD];          // GEMM output  (f32)
__device__ __nv_bfloat16 g_ahi[NN * HD];   // A split hi
__device__ __nv_bfloat16 g_alo[NN * HD];   // A split lo
__device__ __nv_bfloat16 g_wthi[3 * HD * HD];  // W^T split hi  [layer][n][k]
__device__ __nv_bfloat16 g_wtlo[3 * HD * HD];  // W^T split lo
__device__ float g_dinv[NN];
__device__ int   g_rowptr[NN + 1];
__device__ int   g_cnt[NN];
__device__ int   g_fill[NN];
__device__ int   g_col[EE];
__device__ float g_val[EE];
__device__ int   g_gstart[NG + 1];
__device__ float g_pool[NG * HD];
__device__ int   g_bsum[64];

// ---------------- small helpers ----------------
__device__ __forceinline__ uint32_t smem_u32(const void* p) {
    uint32_t a;
    asm("{ .reg .u64 t; cvta.to.shared.u64 t, %1; cvt.u32.u64 %0, t; }"
        : "=r"(a) : "l"(p));
    return a;
}
__device__ __forceinline__ void cp_async16(uint32_t dst, const void* src) {
    asm volatile("cp.async.cg.shared.global [%0], [%1], 16;"
                 :: "r"(dst), "l"(src));
}
#define CP_COMMIT() asm volatile("cp.async.commit_group;")
#define CP_WAIT(n)  asm volatile("cp.async.wait_group %0;" :: "n"(n))

__device__ __forceinline__ void ldsm_x4(uint32_t* r, uint32_t addr) {
    asm volatile("ldmatrix.sync.aligned.m8n8.x4.shared.b16 {%0,%1,%2,%3}, [%4];"
                 : "=r"(r[0]), "=r"(r[1]), "=r"(r[2]), "=r"(r[3]) : "r"(addr));
}
__device__ __forceinline__ void mma_bf16(float* c, const uint32_t* a,
                                         uint32_t b0, uint32_t b1) {
    asm volatile(
        "mma.sync.aligned.m16n8k16.row.col.f32.bf16.bf16.f32 "
        "{%0,%1,%2,%3}, {%4,%5,%6,%7}, {%8,%9}, {%0,%1,%2,%3};"
        : "+f"(c[0]), "+f"(c[1]), "+f"(c[2]), "+f"(c[3])
        : "r"(a[0]), "r"(a[1]), "r"(a[2]), "r"(a[3]), "r"(b0), "r"(b1));
}

// ---------------- setup kernels ----------------
__global__ void init_nodes_kernel() {
    int i = blockIdx.x * blockDim.x + threadIdx.x;
    if (i < NN) { g_cnt[i] = 0; g_fill[i] = 0; }
}
__global__ void count_kernel(const int* __restrict__ ei) {
    int e = blockIdx.x * blockDim.x + threadIdx.x;
    if (e < EE) atomicAdd(&g_cnt[ei[EE + e]], 1);
}
__global__ void scan1_kernel() {   // also computes dinv (deg = cnt + 1 self loop)
    __shared__ int sh[SCAN_B];
    int b = blockIdx.x, t = threadIdx.x;
    int i = b * SCAN_B + t;
    int c = (i < NN) ? g_cnt[i] : 0;
    if (i < NN) g_dinv[i] = rsqrtf((float)(c + 1));
    sh[t] = c;
    __syncthreads();
    #pragma unroll
    for (int off = 1; off < SCAN_B; off <<= 1) {
        int x = (t >= off) ? sh[t - off] : 0;
        __syncthreads();
        sh[t] += x;
        __syncthreads();
    }
    if (i < NN) g_rowptr[i + 1] = sh[t];
    if (t == SCAN_B - 1) g_bsum[b] = sh[t];
}
__global__ void scan2_kernel() {
    __shared__ int sh[64];
    int t = threadIdx.x;
    sh[t] = (t < NBLK) ? g_bsum[t] : 0;
    __syncthreads();
    #pragma unroll
    for (int off = 1; off < 64; off <<= 1) {
        int x = (t >= off) ? sh[t - off] : 0;
        __syncthreads();
        sh[t] += x;
        __syncthreads();
    }
    g_bsum[t] = (t == 0) ? 0 : sh[t - 1];
}
__global__ void scan3_kernel() {
    int b = blockIdx.x, t = threadIdx.x;
    int i = b * SCAN_B + t;
    if (i < NN) g_rowptr[i + 1] += g_bsum[b];
    if (b == 0 && t == 0) g_rowptr[0] = 0;
}
__global__ void fill_kernel(const int* __restrict__ ei) {
    int e = blockIdx.x * blockDim.x + threadIdx.x;
    if (e < EE) {
        int s = ei[e], d = ei[EE + e];
        int p = g_rowptr[d] + atomicAdd(&g_fill[d], 1);
        g_col[p] = s;
        g_val[p] = g_dinv[s];
    }
}
__global__ void gstart_kernel(const int* __restrict__ batch) {
    int g = threadIdx.x;
    if (g > NG) return;
    int lo = 0, hi = NN;
    while (lo < hi) { int m = (lo + hi) >> 1; if (batch[m] < g) lo = m + 1; else hi = m; }
    g_gstart[g] = lo;
}

// ---------------- bf16 split converts ----------------
__device__ __forceinline__ void split_bf16(float v, __nv_bfloat16& hi, __nv_bfloat16& lo) {
    hi = __float2bfloat16(v);
    lo = __float2bfloat16(v - __bfloat162float(hi));
}
__global__ void convert_x_kernel(const float* __restrict__ x) {
    int i = blockIdx.x * blockDim.x + threadIdx.x;
    if (i < NN * HD) {
        __nv_bfloat16 h, l; split_bf16(x[i], h, l);
        g_ahi[i] = h; g_alo[i] = l;
    }
}
__global__ void convert_w_kernel(const float* __restrict__ W0,
                                 const float* __restrict__ W1,
                                 const float* __restrict__ W2) {
    int i = blockIdx.x * blockDim.x + threadIdx.x;
    if (i >= 3 * HD * HD) return;
    int layer = i / (HD * HD), r = i % (HD * HD);
    int n = r / HD, k = r % HD;
    const float* W = (layer == 0) ? W0 : (layer == 1) ? W1 : W2;
    __nv_bfloat16 h, l; split_bf16(W[k * HD + n], h, l);   // Wt[n][k] = W[k][n]
    g_wthi[i] = h; g_wtlo[i] = l;
}

// ---------------- mma.sync GEMM: C[M,256] = A[M,256] @ W[256,256] ---------
// split-2 bf16: C = Ahi*Whi + Ahi*Wlo + Alo*Whi, f32 accum in registers.
// CTA: 128(M) x 128(N), 8 warps (4m x 2n), warp tile 32x64.
// K chunks of 32, 2-stage cp.async double buffer.
// smem tile layout: [row][40] bf16 (stride-40 pad -> conflict-free ldmatrix).
// B tile is W^T[n][k] = col-major B -> plain ldmatrix (NO .trans) gives the
// exact m16n8k16 .col B fragment (lane L: n=L/4, k=(L%4)*2; +8 variants).
#define TS    40                      // tile row stride in elements
#define TBYTES (128 * TS * 2)         // 10240 B per (part) per stage
#define STG_BYTES (4 * TBYTES)        // Ahi,Alo,Bhi,Blo
#define GSMEM (2 * STG_BYTES)         // 81920 B

__global__ void __launch_bounds__(256)
gemm_mma_kernel(const __nv_bfloat16* __restrict__ Ahi,
                const __nv_bfloat16* __restrict__ Alo,
                const __nv_bfloat16* __restrict__ Bhi,
                const __nv_bfloat16* __restrict__ Blo,
                float* __restrict__ C, int M) {
    extern __shared__ char smem[];
    uint32_t sb = smem_u32(smem);
    int tid = threadIdx.x, wid = tid >> 5, lid = tid & 31;
    int bm = blockIdx.x * 128;
    int bn = blockIdx.y * 128;
    int m0 = (wid & 3) * 32, n0 = (wid >> 2) * 64;

    const __nv_bfloat16* srcs[4] = { Ahi, Alo, Bhi, Blo };

    // loader: chunk kc into stage s
    auto load_chunk = [&](int kc, int s) {
        #pragma unroll
        for (int j = 0; j < 8; j++) {
            int idx = tid + j * 256;           // 0..2047
            int part = idx >> 9;               // 0..3
            int r = (idx >> 2) & 127;
            int ch = idx & 3;
            uint32_t dst = sb + s * STG_BYTES + part * TBYTES + (r * TS + ch * 8) * 2;
            int grow = (part < 2) ? (bm + r) : (bn + r);
            if (part >= 2 || grow < M) {
                cp_async16(dst, srcs[part] + grow * 256 + kc * 32 + ch * 8);
            } else {
                uint4 z = make_uint4(0, 0, 0, 0);
                *(uint4*)(smem + (dst - sb)) = z;
            }
        }
        CP_COMMIT();
    };

    float acc[2][8][4];
    #pragma unroll
    for (int i = 0; i < 2; i++)
        #pragma unroll
        for (int j = 0; j < 8; j++)
            #pragma unroll
            for (int q = 0; q < 4; q++) acc[i][j][q] = 0.0f;

    load_chunk(0, 0);
    load_chunk(1, 1);

    // ldmatrix lane address components
    int a_row = lid & 15;
    int a_koff = ((lid >> 4) & 1) * 8;
    int b_n = (lid & 7) + ((lid >> 4) & 1) * 8;
    int b_koff = ((lid >> 3) & 1) * 8;

    for (int kc = 0; kc < 8; kc++) {
        CP_WAIT(1);
        __syncthreads();
        int s = kc & 1;
        uint32_t ah_b = sb + s * STG_BYTES;
        uint32_t al_b = ah_b + TBYTES;
        uint32_t bh_b = al_b + TBYTES;
        uint32_t bl_b = bh_b + TBYTES;

        #pragma unroll
        for (int ks = 0; ks < 2; ks++) {
            int kcol = ks * 16 + a_koff;
            uint32_t ah[2][4], al[2][4];
            #pragma unroll
            for (int mf = 0; mf < 2; mf++) {
                uint32_t off = ((m0 + mf * 16 + a_row) * TS + kcol) * 2;
                ldsm_x4(ah[mf], ah_b + off);
                ldsm_x4(al[mf], al_b + off);
            }
            int kB = ks * 16 + b_koff;
            #pragma unroll
            for (int nf = 0; nf < 4; nf++) {
                uint32_t boff = ((n0 + nf * 16 + b_n) * TS + kB) * 2;
                uint32_t bh[4], bl[4];
                ldsm_x4(bh, bh_b + boff);       // NO .trans: [n][k] is col-major B
                ldsm_x4(bl, bl_b + boff);
                #pragma unroll
                for (int mf = 0; mf < 2; mf++) {
                    mma_bf16(acc[mf][2 * nf],     ah[mf], bh[0], bh[1]);  // hi*hi
                    mma_bf16(acc[mf][2 * nf + 1], ah[mf], bh[2], bh[3]);
                    mma_bf16(acc[mf][2 * nf],     ah[mf], bl[0], bl[1]);  // hi*lo
                    mma_bf16(acc[mf][2 * nf + 1], ah[mf], bl[2], bl[3]);
                    mma_bf16(acc[mf][2 * nf],     al[mf], bh[0], bh[1]);  // lo*hi
                    mma_bf16(acc[mf][2 * nf + 1], al[mf], bh[2], bh[3]);
                }
            }
        }
        __syncthreads();
        if (kc + 2 < 8) load_chunk(kc + 2, s);
    }

    // epilogue: c0,c1 at (row, col..col+1); c2,c3 at (row+8, ...)
    int erow = lid >> 2, ecol = (lid & 3) * 2;
    #pragma unroll
    for (int mf = 0; mf < 2; mf++) {
        #pragma unroll
        for (int nf = 0; nf < 8; nf++) {
            int gr0 = bm + m0 + mf * 16 + erow;
            int gc = bn + n0 + nf * 8 + ecol;
            if (gr0 < M)
                *(float2*)&C[gr0 * 256 + gc] = make_float2(acc[mf][nf][0], acc[mf][nf][1]);
            if (gr0 + 8 < M)
                *(float2*)&C[(gr0 + 8) * 256 + gc] = make_float2(acc[mf][nf][2], acc[mf][nf][3]);
        }
    }
}

// ---------------- aggregation (+ bf16 split of output for next layer) -----
__global__ void __launch_bounds__(HD)
agg_kernel(const float* __restrict__ hw, const float* __restrict__ bias,
           float* __restrict__ out) {
    int node = blockIdx.x;
    int t = threadIdx.x;
    int beg = g_rowptr[node], end = g_rowptr[node + 1];
    float di = g_dinv[node];
    float acc = di * hw[node * HD + t];
    for (int p = beg; p < end; p++) {
        int s = g_col[p];
        float w = g_val[p];
        acc += w * hw[s * HD + t];
    }
    float r = fmaxf(fmaf(acc, di, bias[t]), 0.0f);
    out[node * HD + t] = r;
    __nv_bfloat16 h, l; split_bf16(r, h, l);
    g_ahi[node * HD + t] = h;
    g_alo[node * HD + t] = l;
}

// ---------------- mean pool + classifier head -----------------------------
__global__ void pool_kernel(const float* __restrict__ h) {
    int g = blockIdx.x, t = threadIdx.x;
    int s = g_gstart[g], e = g_gstart[g + 1];
    float acc = 0.0f;
    for (int n = s; n < e; n++) acc += h[n * HD + t];
    float c = (float)(e - s);
    g_pool[g * HD + t] = acc / fmaxf(c, 1.0f);
}
__global__ void __launch_bounds__(128)
classifier_kernel(const float* __restrict__ cW1, const float* __restrict__ cb1,
                  const float* __restrict__ cW2, const float* __restrict__ cb2,
                  float* __restrict__ out) {
    __shared__ float sp[HD];
    __shared__ float sz[128];
    int g = blockIdx.x, t = threadIdx.x;
    sp[t]       = g_pool[g * HD + t];
    sp[t + 128] = g_pool[g * HD + t + 128];
    __syncthreads();
    float acc = cb1[t];
    #pragma unroll 4
    for (int k = 0; k < HD; k++) acc = fmaf(sp[k], cW1[k * 128 + t], acc);
    sz[t] = fmaxf(acc, 0.0f);
    __syncthreads();
    if (t < 16) {
        float a = cb2[t];
        #pragma unroll 4
        for (int j = 0; j < 128; j++) a = fmaf(sz[j], cW2[j * 16 + t], a);
        out[g * 16 + t] = a;
    }
}

// ---------------- launch --------------------------------------------------
extern "C" void kernel_launch(void* const* d_in, const int* in_sizes, int n_in,
                              void* d_out, int out_size) {
    const void* p_x = 0; const void* p_ei = 0; const void* p_batch = 0;
    const void* p_W[3] = {0, 0, 0}; int nW = 0;
    const void* p_b[3] = {0, 0, 0}; int nb = 0;
    const void* p_cW1 = 0; const void* p_cb1 = 0;
    const void* p_cW2 = 0; const void* p_cb2 = 0;
    for (int i = 0; i < n_in; i++) {
        int sz = in_sizes[i]; const void* p = d_in[i];
        if      (sz == NN * HD)  p_x = p;
        else if (sz == 2 * EE)   p_ei = p;
        else if (sz == NN)       p_batch = p;
        else if (sz == HD * HD)  { if (nW < 3) p_W[nW++] = p; }
        else if (sz == HD)       { if (nb < 3) p_b[nb++] = p; }
        else if (sz == HD * 128) p_cW1 = p;
        else if (sz == 128)      p_cb1 = p;
        else if (sz == 128 * 16) p_cW2 = p;
        else if (sz == 16)       p_cb2 = p;
    }
    const float* x     = (const float*)p_x;
    const int*   ei    = (const int*)p_ei;
    const int*   batch = (const int*)p_batch;
    const float* W0 = (const float*)p_W[0]; const float* b0 = (const float*)p_b[0];
    const float* W1 = (const float*)p_W[1]; const float* b1 = (const float*)p_b[1];
    const float* W2 = (const float*)p_W[2]; const float* b2 = (const float*)p_b[2];
    const float* cW1 = (const float*)p_cW1; const float* cb1 = (const float*)p_cb1;
    const float* cW2 = (const float*)p_cW2; const float* cb2 = (const float*)p_cb2;
    float* out = (float*)d_out;

    float* bufA; cudaGetSymbolAddress((void**)&bufA, g_bufA);
    float* bufB; cudaGetSymbolAddress((void**)&bufB, g_bufB);
    __nv_bfloat16* ahi; cudaGetSymbolAddress((void**)&ahi, g_ahi);
    __nv_bfloat16* alo; cudaGetSymbolAddress((void**)&alo, g_alo);
    __nv_bfloat16* wthi; cudaGetSymbolAddress((void**)&wthi, g_wthi);
    __nv_bfloat16* wtlo; cudaGetSymbolAddress((void**)&wtlo, g_wtlo);

    static bool attr_set = false;
    if (!attr_set) {
        cudaFuncSetAttribute(gemm_mma_kernel,
                             cudaFuncAttributeMaxDynamicSharedMemorySize, GSMEM);
        attr_set = true;
    }

    // graph structure + weight conversion
    init_nodes_kernel<<<(NN + 255) / 256, 256>>>();
    count_kernel<<<(EE + 255) / 256, 256>>>(ei);
    scan1_kernel<<<NBLK, SCAN_B>>>();
    scan2_kernel<<<1, 64>>>();
    scan3_kernel<<<NBLK, SCAN_B>>>();
    fill_kernel<<<(EE + 255) / 256, 256>>>(ei);
    gstart_kernel<<<1, NG + 1>>>(batch);
    convert_w_kernel<<<(3 * HD * HD + 255) / 256, 256>>>(W0, W1, W2);
    convert_x_kernel<<<(NN * HD + 255) / 256, 256>>>(x);

    dim3 ggrid(MTILES, 2);

    // layer 1
    gemm_mma_kernel<<<ggrid, 256, GSMEM>>>(ahi, alo, wthi, wtlo, bufB, NN);
    agg_kernel<<<NN, HD>>>(bufB, b0, bufA);
    // layer 2
    gemm_mma_kernel<<<ggrid, 256, GSMEM>>>(ahi, alo, wthi + 65536, wtlo + 65536, bufB, NN);
    agg_kernel<<<NN, HD>>>(bufB, b1, bufA);
    // layer 3
    gemm_mma_kernel<<<ggrid, 256, GSMEM>>>(ahi, alo, wthi + 131072, wtlo + 131072, bufB, NN);
    agg_kernel<<<NN, HD>>>(bufB, b2, bufA);

    // pool + head
    pool_kernel<<<NG, HD>>>(bufA);
    classifier_kernel<<<NG, 128>>>(cW1, cb1, cW2, cb2, out);
}

// round 9
// speedup vs baseline: 1.3767x; 1.0138x over previous
#include <cuda_runtime.h>
#include <cuda_bf16.h>
#include <cstdint>

// ---------------- problem constants ----------------
#define NN   50000
#define EE   600000
#define HD   256
#define NG   64
#define SCAN_B 1024
#define NBLK ((NN + SCAN_B - 1) / SCAN_B)   // 49
#define MTILES ((NN + 127) / 128)           // 391

// ---------------- device scratch -------------------
__device__ float g_bufA[NN * HD];          // layer-3 output (f32, for pool)
__device__ float g_bufB[NN * HD];          // GEMM output  (f32)
__device__ __nv_bfloat16 g_ahi[NN * HD];   // A split hi
__device__ __nv_bfloat16 g_alo[NN * HD];   // A split lo
__device__ __nv_bfloat16 g_wthi[3 * HD * HD];  // W^T split hi  [layer][n][k]
__device__ __nv_bfloat16 g_wtlo[3 * HD * HD];  // W^T split lo
__device__ float g_dinv[NN];
__device__ int   g_rowptr[NN + 1];
__device__ int   g_cnt[NN];
__device__ int   g_fill[NN];
__device__ int   g_col[EE];
__device__ float g_val[EE];
__device__ int   g_gstart[NG + 1];
__device__ float g_pool[NG * HD];
__device__ int   g_bsum[64];

// ---------------- small helpers ----------------
__device__ __forceinline__ uint32_t smem_u32(const void* p) {
    uint32_t a;
    asm("{ .reg .u64 t; cvta.to.shared.u64 t, %1; cvt.u32.u64 %0, t; }"
        : "=r"(a) : "l"(p));
    return a;
}
__device__ __forceinline__ void cp_async16(uint32_t dst, const void* src) {
    asm volatile("cp.async.cg.shared.global [%0], [%1], 16;"
                 :: "r"(dst), "l"(src));
}
#define CP_COMMIT() asm volatile("cp.async.commit_group;")
#define CP_WAIT(n)  asm volatile("cp.async.wait_group %0;" :: "n"(n))

__device__ __forceinline__ void ldsm_x4(uint32_t* r, uint32_t addr) {
    asm volatile("ldmatrix.sync.aligned.m8n8.x4.shared.b16 {%0,%1,%2,%3}, [%4];"
                 : "=r"(r[0]), "=r"(r[1]), "=r"(r[2]), "=r"(r[3]) : "r"(addr));
}
__device__ __forceinline__ void mma_bf16(float* c, const uint32_t* a,
                                         uint32_t b0, uint32_t b1) {
    asm volatile(
        "mma.sync.aligned.m16n8k16.row.col.f32.bf16.bf16.f32 "
        "{%0,%1,%2,%3}, {%4,%5,%6,%7}, {%8,%9}, {%0,%1,%2,%3};"
        : "+f"(c[0]), "+f"(c[1]), "+f"(c[2]), "+f"(c[3])
        : "r"(a[0]), "r"(a[1]), "r"(a[2]), "r"(a[3]), "r"(b0), "r"(b1));
}
__device__ __forceinline__ void split_bf16(float v, __nv_bfloat16& hi, __nv_bfloat16& lo) {
    hi = __float2bfloat16(v);
    lo = __float2bfloat16(v - __bfloat162float(hi));
}

// ---------------- setup kernels ----------------
__global__ void init_nodes_kernel() {
    int i = blockIdx.x * blockDim.x + threadIdx.x;
    if (i < NN) { g_cnt[i] = 0; g_fill[i] = 0; }
}
// count + (block 0) graph-boundary binary search
__global__ void count_kernel(const int* __restrict__ ei, const int* __restrict__ batch) {
    int e = blockIdx.x * blockDim.x + threadIdx.x;
    if (e < EE) atomicAdd(&g_cnt[ei[EE + e]], 1);
    if (blockIdx.x == 0 && threadIdx.x <= NG) {
        int g = threadIdx.x;
        int lo = 0, hi = NN;
        while (lo < hi) { int m = (lo + hi) >> 1; if (batch[m] < g) lo = m + 1; else hi = m; }
        g_gstart[g] = lo;
    }
}
__global__ void scan1_kernel() {   // per-block inclusive scan + dinv (deg = cnt+1)
    __shared__ int sh[SCAN_B];
    int b = blockIdx.x, t = threadIdx.x;
    int i = b * SCAN_B + t;
    int c = (i < NN) ? g_cnt[i] : 0;
    if (i < NN) g_dinv[i] = rsqrtf((float)(c + 1));
    sh[t] = c;
    __syncthreads();
    #pragma unroll
    for (int off = 1; off < SCAN_B; off <<= 1) {
        int x = (t >= off) ? sh[t - off] : 0;
        __syncthreads();
        sh[t] += x;
        __syncthreads();
    }
    if (i < NN) g_rowptr[i + 1] = sh[t];
    if (t == SCAN_B - 1) g_bsum[b] = sh[t];
}
__global__ void scan3_kernel() {   // add exclusive prefix of block sums (computed locally)
    __shared__ int pref;
    int b = blockIdx.x, t = threadIdx.x;
    if (t == 0) {
        int s = 0;
        for (int i = 0; i < b; i++) s += g_bsum[i];
        pref = s;
    }
    __syncthreads();
    int i = b * SCAN_B + t;
    if (i < NN) g_rowptr[i + 1] += pref;
    if (b == 0 && t == 0) g_rowptr[0] = 0;
}
__global__ void fill_kernel(const int* __restrict__ ei) {
    int e = blockIdx.x * blockDim.x + threadIdx.x;
    if (e < EE) {
        int s = ei[e], d = ei[EE + e];
        int p = g_rowptr[d] + atomicAdd(&g_fill[d], 1);
        g_col[p] = s;
        g_val[p] = g_dinv[s];
    }
}
__global__ void convert_w_kernel(const float* __restrict__ W0,
                                 const float* __restrict__ W1,
                                 const float* __restrict__ W2) {
    int i = blockIdx.x * blockDim.x + threadIdx.x;
    if (i >= 3 * HD * HD) return;
    int layer = i / (HD * HD), r = i % (HD * HD);
    int n = r / HD, k = r % HD;
    const float* W = (layer == 0) ? W0 : (layer == 1) ? W1 : W2;
    __nv_bfloat16 h, l; split_bf16(W[k * HD + n], h, l);   // Wt[n][k] = W[k][n]
    g_wthi[i] = h; g_wtlo[i] = l;
}

// ---------------- mma.sync GEMM: C[M,256] = A[M,256] @ W[256,256] ---------
// split-2 bf16: C = Ahi*Whi + Ahi*Wlo + Alo*Whi, f32 accum in registers.
// CTA: 128(M) x 128(N), 8 warps (4m x 2n), warp tile 32x64.
// K chunks of 32, 2-stage cp.async double buffer.
// smem tile [row][40] bf16; B tile is W^T[n][k] (col-major B) -> plain ldmatrix.
// If Af32 != null (layer 1), A is loaded as f32 and split hi/lo in the loader.
#define TS    40
#define TBYTES (128 * TS * 2)         // 10240 B per part per stage
#define STG_BYTES (4 * TBYTES)        // Ahi,Alo,Bhi,Blo
#define GSMEM (2 * STG_BYTES)         // 81920 B

__global__ void __launch_bounds__(256)
gemm_mma_kernel(const float* __restrict__ Af32,
                const __nv_bfloat16* __restrict__ Ahi,
                const __nv_bfloat16* __restrict__ Alo,
                const __nv_bfloat16* __restrict__ Bhi,
                const __nv_bfloat16* __restrict__ Blo,
                float* __restrict__ C, int M) {
    extern __shared__ char smem[];
    uint32_t sb = smem_u32(smem);
    int tid = threadIdx.x, wid = tid >> 5, lid = tid & 31;
    int bm = blockIdx.x * 128;
    int bn = blockIdx.y * 128;
    int m0 = (wid & 3) * 32, n0 = (wid >> 2) * 64;

    const __nv_bfloat16* srcs[4] = { Ahi, Alo, Bhi, Blo };

    auto load_chunk = [&](int kc, int s) {
        if (Af32) {
            // A from f32 (split on the fly), B via cp.async. 1536 tasks.
            #pragma unroll
            for (int j = 0; j < 6; j++) {
                int idx = tid + j * 256;
                if (idx < 512) {                      // A task: r,ch -> hi+lo 16B each
                    int r = idx >> 2, ch = idx & 3;
                    uint32_t off = (uint32_t)(r * TS + ch * 8) * 2;
                    uint32_t base = s * STG_BYTES;
                    union { __nv_bfloat16 v[8]; uint4 u; } Hh, Ll;
                    int gr = bm + r;
                    if (gr < M) {
                        const float* src = Af32 + gr * 256 + kc * 32 + ch * 8;
                        float4 f0 = *(const float4*)src;
                        float4 f1 = *(const float4*)(src + 4);
                        float fv[8] = { f0.x, f0.y, f0.z, f0.w, f1.x, f1.y, f1.z, f1.w };
                        #pragma unroll
                        for (int q = 0; q < 8; q++) split_bf16(fv[q], Hh.v[q], Ll.v[q]);
                    } else {
                        Hh.u = make_uint4(0, 0, 0, 0); Ll.u = Hh.u;
                    }
                    *(uint4*)(smem + base + off) = Hh.u;
                    *(uint4*)(smem + base + TBYTES + off) = Ll.u;
                } else {                              // B task
                    int q = idx - 512;                // [0,1024)
                    int part = 2 + (q >> 9);
                    int r = (q >> 2) & 127, ch = q & 3;
                    uint32_t dst = sb + s * STG_BYTES + part * TBYTES + (r * TS + ch * 8) * 2;
                    cp_async16(dst, srcs[part] + (bn + r) * 256 + kc * 32 + ch * 8);
                }
            }
        } else {
            #pragma unroll
            for (int j = 0; j < 8; j++) {
                int idx = tid + j * 256;              // 0..2047
                int part = idx >> 9;
                int r = (idx >> 2) & 127, ch = idx & 3;
                uint32_t dst = sb + s * STG_BYTES + part * TBYTES + (r * TS + ch * 8) * 2;
                int grow = (part < 2) ? (bm + r) : (bn + r);
                if (part >= 2 || grow < M) {
                    cp_async16(dst, srcs[part] + grow * 256 + kc * 32 + ch * 8);
                } else {
                    uint4 z = make_uint4(0, 0, 0, 0);
                    *(uint4*)(smem + (dst - sb)) = z;
                }
            }
        }
        CP_COMMIT();
    };

    float acc[2][8][4];
    #pragma unroll
    for (int i = 0; i < 2; i++)
        #pragma unroll
        for (int j = 0; j < 8; j++)
            #pragma unroll
            for (int q = 0; q < 4; q++) acc[i][j][q] = 0.0f;

    load_chunk(0, 0);
    load_chunk(1, 1);

    int a_row = lid & 15;
    int a_koff = ((lid >> 4) & 1) * 8;
    int b_n = (lid & 7) + ((lid >> 4) & 1) * 8;
    int b_koff = ((lid >> 3) & 1) * 8;

    for (int kc = 0; kc < 8; kc++) {
        CP_WAIT(1);
        __syncthreads();
        int s = kc & 1;
        uint32_t ah_b = sb + s * STG_BYTES;
        uint32_t al_b = ah_b + TBYTES;
        uint32_t bh_b = al_b + TBYTES;
        uint32_t bl_b = bh_b + TBYTES;

        #pragma unroll
        for (int ks = 0; ks < 2; ks++) {
            int kcol = ks * 16 + a_koff;
            uint32_t ah[2][4], al[2][4];
            #pragma unroll
            for (int mf = 0; mf < 2; mf++) {
                uint32_t off = ((m0 + mf * 16 + a_row) * TS + kcol) * 2;
                ldsm_x4(ah[mf], ah_b + off);
                ldsm_x4(al[mf], al_b + off);
            }
            int kB = ks * 16 + b_koff;
            #pragma unroll
            for (int nf = 0; nf < 4; nf++) {
                uint32_t boff = ((n0 + nf * 16 + b_n) * TS + kB) * 2;
                uint32_t bh[4], bl[4];
                ldsm_x4(bh, bh_b + boff);       // no .trans: [n][k] is col-major B
                ldsm_x4(bl, bl_b + boff);
                #pragma unroll
                for (int mf = 0; mf < 2; mf++) {
                    mma_bf16(acc[mf][2 * nf],     ah[mf], bh[0], bh[1]);  // hi*hi
                    mma_bf16(acc[mf][2 * nf + 1], ah[mf], bh[2], bh[3]);
                    mma_bf16(acc[mf][2 * nf],     ah[mf], bl[0], bl[1]);  // hi*lo
                    mma_bf16(acc[mf][2 * nf + 1], ah[mf], bl[2], bl[3]);
                    mma_bf16(acc[mf][2 * nf],     al[mf], bh[0], bh[1]);  // lo*hi
                    mma_bf16(acc[mf][2 * nf + 1], al[mf], bh[2], bh[3]);
                }
            }
        }
        __syncthreads();
        if (kc + 2 < 8) load_chunk(kc + 2, s);
    }

    int erow = lid >> 2, ecol = (lid & 3) * 2;
    #pragma unroll
    for (int mf = 0; mf < 2; mf++) {
        #pragma unroll
        for (int nf = 0; nf < 8; nf++) {
            int gr0 = bm + m0 + mf * 16 + erow;
            int gc = bn + n0 + nf * 8 + ecol;
            if (gr0 < M)
                *(float2*)&C[gr0 * 256 + gc] = make_float2(acc[mf][nf][0], acc[mf][nf][1]);
            if (gr0 + 8 < M)
                *(float2*)&C[(gr0 + 8) * 256 + gc] = make_float2(acc[mf][nf][2], acc[mf][nf][3]);
        }
    }
}

// ---------------- aggregation -----------------------------------------
// out = relu(dinv_d*(sum val*hw[col] + dinv_d*hw[d]) + b)
// STORE_F32: write f32 result (only needed before pool, layer 3)
// SPLIT:     write bf16 hi/lo (only needed before next GEMM, layers 1-2)
template <bool STORE_F32, bool SPLIT>
__global__ void __launch_bounds__(HD)
agg_kernel(const float* __restrict__ hw, const float* __restrict__ bias,
           float* __restrict__ out) {
    int node = blockIdx.x;
    int t = threadIdx.x;
    int beg = g_rowptr[node], end = g_rowptr[node + 1];
    float di = g_dinv[node];
    float acc = di * hw[node * HD + t];
    int p = beg;
    for (; p + 4 <= end; p += 4) {            // 4 independent gathers -> MLP 4
        int s0 = g_col[p], s1 = g_col[p + 1], s2 = g_col[p + 2], s3 = g_col[p + 3];
        float w0 = g_val[p], w1 = g_val[p + 1], w2 = g_val[p + 2], w3 = g_val[p + 3];
        float v0 = hw[s0 * HD + t];
        float v1 = hw[s1 * HD + t];
        float v2 = hw[s2 * HD + t];
        float v3 = hw[s3 * HD + t];
        acc = fmaf(w0, v0, acc);
        acc = fmaf(w1, v1, acc);
        acc = fmaf(w2, v2, acc);
        acc = fmaf(w3, v3, acc);
    }
    for (; p < end; p++) {
        int s = g_col[p];
        acc = fmaf(g_val[p], hw[s * HD + t], acc);
    }
    float r = fmaxf(fmaf(acc, di, bias[t]), 0.0f);
    if (STORE_F32) out[node * HD + t] = r;
    if (SPLIT) {
        __nv_bfloat16 h, l; split_bf16(r, h, l);
        g_ahi[node * HD + t] = h;
        g_alo[node * HD + t] = l;
    }
}

// ---------------- mean pool + classifier head -----------------------------
__global__ void pool_kernel(const float* __restrict__ h) {
    int g = blockIdx.x, t = threadIdx.x;
    int s = g_gstart[g], e = g_gstart[g + 1];
    float a0 = 0.f, a1 = 0.f, a2 = 0.f, a3 = 0.f;
    int n = s;
    for (; n + 4 <= e; n += 4) {
        a0 += h[n * HD + t];
        a1 += h[(n + 1) * HD + t];
        a2 += h[(n + 2) * HD + t];
        a3 += h[(n + 3) * HD + t];
    }
    for (; n < e; n++) a0 += h[n * HD + t];
    float acc = (a0 + a1) + (a2 + a3);
    float c = (float)(e - s);
    g_pool[g * HD + t] = acc / fmaxf(c, 1.0f);
}
__global__ void __launch_bounds__(128)
classifier_kernel(const float* __restrict__ cW1, const float* __restrict__ cb1,
                  const float* __restrict__ cW2, const float* __restrict__ cb2,
                  float* __restrict__ out) {
    __shared__ float sp[HD];
    __shared__ float sz[128];
    int g = blockIdx.x, t = threadIdx.x;
    sp[t]       = g_pool[g * HD + t];
    sp[t + 128] = g_pool[g * HD + t + 128];
    __syncthreads();
    float acc = cb1[t];
    #pragma unroll 4
    for (int k = 0; k < HD; k++) acc = fmaf(sp[k], cW1[k * 128 + t], acc);
    sz[t] = fmaxf(acc, 0.0f);
    __syncthreads();
    if (t < 16) {
        float a = cb2[t];
        #pragma unroll 4
        for (int j = 0; j < 128; j++) a = fmaf(sz[j], cW2[j * 16 + t], a);
        out[g * 16 + t] = a;
    }
}

// ---------------- launch --------------------------------------------------
extern "C" void kernel_launch(void* const* d_in, const int* in_sizes, int n_in,
                              void* d_out, int out_size) {
    const void* p_x = 0; const void* p_ei = 0; const void* p_batch = 0;
    const void* p_W[3] = {0, 0, 0}; int nW = 0;
    const void* p_b[3] = {0, 0, 0}; int nb = 0;
    const void* p_cW1 = 0; const void* p_cb1 = 0;
    const void* p_cW2 = 0; const void* p_cb2 = 0;
    for (int i = 0; i < n_in; i++) {
        int sz = in_sizes[i]; const void* p = d_in[i];
        if      (sz == NN * HD)  p_x = p;
        else if (sz == 2 * EE)   p_ei = p;
        else if (sz == NN)       p_batch = p;
        else if (sz == HD * HD)  { if (nW < 3) p_W[nW++] = p; }
        else if (sz == HD)       { if (nb < 3) p_b[nb++] = p; }
        else if (sz == HD * 128) p_cW1 = p;
        else if (sz == 128)      p_cb1 = p;
        else if (sz == 128 * 16) p_cW2 = p;
        else if (sz == 16)       p_cb2 = p;
    }
    const float* x     = (const float*)p_x;
    const int*   ei    = (const int*)p_ei;
    const int*   batch = (const int*)p_batch;
    const float* W0 = (const float*)p_W[0]; const float* b0 = (const float*)p_b[0];
    const float* W1 = (const float*)p_W[1]; const float* b1 = (const float*)p_b[1];
    const float* W2 = (const float*)p_W[2]; const float* b2 = (const float*)p_b[2];
    const float* cW1 = (const float*)p_cW1; const float* cb1 = (const float*)p_cb1;
    const float* cW2 = (const float*)p_cW2; const float* cb2 = (const float*)p_cb2;
    float* out = (float*)d_out;

    float* bufA; cudaGetSymbolAddress((void**)&bufA, g_bufA);
    float* bufB; cudaGetSymbolAddress((void**)&bufB, g_bufB);
    __nv_bfloat16* ahi; cudaGetSymbolAddress((void**)&ahi, g_ahi);
    __nv_bfloat16* alo; cudaGetSymbolAddress((void**)&alo, g_alo);
    __nv_bfloat16* wthi; cudaGetSymbolAddress((void**)&wthi, g_wthi);
    __nv_bfloat16* wtlo; cudaGetSymbolAddress((void**)&wtlo, g_wtlo);

    cudaFuncSetAttribute(gemm_mma_kernel,
                         cudaFuncAttributeMaxDynamicSharedMemorySize, GSMEM);

    dim3 ggrid(MTILES, 2);

    // order chosen so gemm layer-1 is the 4th launch (ncu profiles slot 4)
    init_nodes_kernel<<<(NN + 255) / 256, 256>>>();                       // 1
    count_kernel<<<(EE + 255) / 256, 256>>>(ei, batch);                   // 2
    convert_w_kernel<<<(3 * HD * HD + 255) / 256, 256>>>(W0, W1, W2);     // 3
    // layer 1 GEMM (f32 A, split in loader)
    gemm_mma_kernel<<<ggrid, 256, GSMEM>>>(x, 0, 0, wthi, wtlo, bufB, NN);          // 4
    // CSR build (needed before agg)
    scan1_kernel<<<NBLK, SCAN_B>>>();                                     // 5
    scan3_kernel<<<NBLK, SCAN_B>>>();                                     // 6
    fill_kernel<<<(EE + 255) / 256, 256>>>(ei);                           // 7
    agg_kernel<false, true><<<NN, HD>>>(bufB, b0, bufA);                  // 8
    // layer 2
    gemm_mma_kernel<<<ggrid, 256, GSMEM>>>(0, ahi, alo, wthi + 65536, wtlo + 65536, bufB, NN);
    agg_kernel<false, true><<<NN, HD>>>(bufB, b1, bufA);
    // layer 3
    gemm_mma_kernel<<<ggrid, 256, GSMEM>>>(0, ahi, alo, wthi + 131072, wtlo + 131072, bufB, NN);
    agg_kernel<true, false><<<NN, HD>>>(bufB, b2, bufA);
    // pool + head
    pool_kernel<<<NG, HD>>>(bufA);
    classifier_kernel<<<NG, 128>>>(cW1, cb1, cW2, cb2, out);
}